// round 5
// baseline (speedup 1.0000x reference)
#include <cuda_runtime.h>

// NCC loss, 9x9 box window, zero padding, win_size fixed at 81.
// inputs: predict [32,1,512,512] f32, target [32,1,512,512] f32
// output: scalar f32 = 1 - mean(cross^2 / (Ivar*Jvar + 1e-6))

constexpr int W      = 512;
constexpr int H      = 512;
constexpr int BATCH  = 32;
constexpr int ROWS   = 64;            // output rows per block
constexpr int STRIPS = H / ROWS;      // 8
constexpr int NBLK   = BATCH * STRIPS; // 256
constexpr int TPB    = 512;           // one thread per column
constexpr float INV81 = 1.0f / 81.0f;

__device__ float g_partials[NBLK];

__global__ void __launch_bounds__(TPB, 1)
ncc_main_kernel(const float* __restrict__ gI, const float* __restrict__ gJ) {
    __shared__ float sI[2][W + 8];
    __shared__ float sJ[2][W + 8];
    __shared__ float s_wsum[TPB / 32];

    const int x  = threadIdx.x;                    // column 0..511
    const int y0 = blockIdx.x * ROWS;              // strip start row
    const size_t base = (size_t)blockIdx.y * (size_t)(H * W);
    const float* Ib = gI + base;
    const float* Jb = gJ + base;

    // zero-pad halos (written once, never overwritten)
    if (x < 4) {
        sI[0][x] = 0.f; sI[1][x] = 0.f;
        sJ[0][x] = 0.f; sJ[1][x] = 0.f;
        sI[0][W + 4 + x] = 0.f; sI[1][W + 4 + x] = 0.f;
        sJ[0][W + 4 + x] = 0.f; sJ[1][W + 4 + x] = 0.f;
    }

    // 9-deep register ring buffers of horizontal sums (static indexing via unroll)
    float hsI[9], hsJ[9], hsI2[9], hsJ2[9], hsIJ[9];
#pragma unroll
    for (int k = 0; k < 9; ++k) {
        hsI[k] = 0.f; hsJ[k] = 0.f; hsI2[k] = 0.f; hsJ2[k] = 0.f; hsIJ[k] = 0.f;
    }
    float VI = 0.f, VJ = 0.f, VI2 = 0.f, VJ2 = 0.f, VIJ = 0.f;
    float acc = 0.f;

#pragma unroll 1
    for (int m = 0; m < 8; ++m) {
#pragma unroll
        for (int k = 0; k < 9; ++k) {            // it = m*9 + k, ring slot = k
            const int it = m * 9 + k;
            const int r  = y0 - 4 + it;          // input row (may be out of range -> zeros)

            float iv = 0.f, jv = 0.f;
            if ((unsigned)r < (unsigned)H) {
                iv = Ib[r * W + x];
                jv = Jb[r * W + x];
            }
            const int buf = it & 1;
            sI[buf][4 + x] = iv;
            sJ[buf][4 + x] = jv;
            __syncthreads();

            // horizontal 9-tap for the 5 quantities
            float hI = 0.f, hJ = 0.f, hI2 = 0.f, hJ2 = 0.f, hIJ = 0.f;
#pragma unroll
            for (int t = 0; t < 9; ++t) {
                const float a = sI[buf][x + t];
                const float c = sJ[buf][x + t];
                hI += a;
                hJ += c;
                hI2 = fmaf(a, a, hI2);
                hJ2 = fmaf(c, c, hJ2);
                hIJ = fmaf(a, c, hIJ);
            }

            // vertical running 9-window (add new row, drop row from 9 iters ago)
            VI  += hI  - hsI[k];   hsI[k]  = hI;
            VJ  += hJ  - hsJ[k];   hsJ[k]  = hJ;
            VI2 += hI2 - hsI2[k];  hsI2[k] = hI2;
            VJ2 += hJ2 - hsJ2[k];  hsJ2[k] = hJ2;
            VIJ += hIJ - hsIJ[k];  hsIJ[k] = hIJ;

            if (it >= 8) {   // output row y = y0 + it - 8 is complete
                const float tI    = VI * INV81;
                const float tJ    = VJ * INV81;
                const float cross = fmaf(-tI, VJ, VIJ);   // IJ - Isum*Jsum/81
                const float Ivar  = fmaf(-tI, VI, VI2);   // I2 - Isum^2/81
                const float Jvar  = fmaf(-tJ, VJ, VJ2);   // J2 - Jsum^2/81
                const float denom = fmaf(Ivar, Jvar, 1e-6f);
                acc += __fdividef(cross * cross, denom);
            }
        }
    }

    // deterministic block reduction
#pragma unroll
    for (int o = 16; o > 0; o >>= 1) acc += __shfl_xor_sync(0xffffffffu, acc, o);
    if ((x & 31) == 0) s_wsum[x >> 5] = acc;
    __syncthreads();
    if (x < 16) {
        float v = s_wsum[x];
#pragma unroll
        for (int o = 8; o > 0; o >>= 1) v += __shfl_xor_sync(0x0000ffffu, v, o);
        if (x == 0) g_partials[blockIdx.y * STRIPS + blockIdx.x] = v;
    }
}

__global__ void ncc_finalize_kernel(float* __restrict__ out) {
    __shared__ float s_wsum[NBLK / 32];   // 8
    const int t = threadIdx.x;            // 256 threads
    float v = g_partials[t];
#pragma unroll
    for (int o = 16; o > 0; o >>= 1) v += __shfl_xor_sync(0xffffffffu, v, o);
    if ((t & 31) == 0) s_wsum[t >> 5] = v;
    __syncthreads();
    if (t < 8) {
        float s = s_wsum[t];
#pragma unroll
        for (int o = 4; o > 0; o >>= 1) s += __shfl_xor_sync(0x000000ffu, s, o);
        if (t == 0) {
            // N = 32*512*512 = 2^23 ; 1/N exact in f32
            out[0] = 1.0f - s * (1.0f / 8388608.0f);
        }
    }
}

extern "C" void kernel_launch(void* const* d_in, const int* in_sizes, int n_in,
                              void* d_out, int out_size) {
    const float* predict = (const float*)d_in[0];
    const float* target  = (const float*)d_in[1];
    dim3 grid(STRIPS, BATCH);
    ncc_main_kernel<<<grid, TPB>>>(predict, target);
    ncc_finalize_kernel<<<1, NBLK>>>((float*)d_out);
}